// round 12
// baseline (speedup 1.0000x reference)
#include <cuda_runtime.h>
#include <math.h>

#define N_NODES 100000
#define N_EDGES 1600000
#define IN_DIM 128
#define HID 64
#define OUT_DIM 40
#define NTILES ((N_NODES + 255) / 256)   // 391
#define N_NODE_TILES (N_NODES / 16)      // 6250
#define PERSIST_GRID 1184                // 8 blocks/SM * 148 SMs

// ---------------- scratch (__device__ globals; referenced from DEVICE code only) ----------------
__device__ int d_is64;                         // 1 if edge_index delivered as int64
__device__ __align__(16) int d_src[N_EDGES];   // canonical int32 src
__device__ __align__(16) int d_dst[N_EDGES];   // canonical int32 dst
__device__ __align__(16) int d_cnt[N_NODES];
__device__ __align__(16) int d_rowptr[N_NODES + 1];
__device__ __align__(16) int d_bsum[512];
__device__ __align__(16) int d_boff[512];
__device__ __align__(16) int d_eidx[N_EDGES];
__device__ __align__(16) float d_dinv[N_NODES];
__device__ __align__(16) float d_g1[(size_t)N_NODES * HID];   // (x@W1)*dinv
__device__ __align__(16) float d_g2[(size_t)N_NODES * HID];   // (h1@W2)*dinv

// ---------------- detect dtype + zero d_cnt (fused) ----------------
__global__ void detect_zero_kernel(const int* __restrict__ ei32) {
    int i = blockIdx.x * blockDim.x + threadIdx.x;
    if (i < N_NODES) d_cnt[i] = 0;
    if (blockIdx.x == 0) {
        __shared__ int any_nonzero;
        if (threadIdx.x == 0) any_nonzero = 0;
        __syncthreads();
        int local = 0;
        for (int k = threadIdx.x; k < 2048; k += blockDim.x)
            local |= ei32[2 * k + 1];
        if (local) atomicOr(&any_nonzero, 1);
        __syncthreads();
        if (threadIdx.x == 0) d_is64 = (any_nonzero == 0) ? 1 : 0;
    }
}

// convert to canonical int32 + in-degree histogram, one pass
__global__ void convert_hist_kernel(const int* __restrict__ ei32) {
    int e = blockIdx.x * blockDim.x + threadIdx.x;
    if (e >= N_EDGES) return;
    int s, d;
    if (d_is64) {   // coalesced 8B loads; low word holds the value (LE)
        const long long* e64 = (const long long*)ei32;
        s = (int)e64[e];
        d = (int)e64[N_EDGES + e];
    } else {
        s = ei32[e];
        d = ei32[N_EDGES + e];
    }
    s = min(max(s, 0), N_NODES - 1);   // clamp: no wild addresses downstream
    d = min(max(d, 0), N_NODES - 1);
    d_src[e] = s;
    d_dst[e] = d;
    atomicAdd(&d_cnt[d], 1);
}

// per-256-tile inclusive scan of degrees; also computes dinv and re-zeroes d_cnt
__global__ void scanA_kernel() {
    __shared__ int s[256];
    int t = threadIdx.x;
    int i = blockIdx.x * 256 + t;
    int v = (i < N_NODES) ? d_cnt[i] : 0;
    if (i < N_NODES) {
        d_dinv[i] = rsqrtf((float)v + 1.0f);  // +1 self-loop
        d_cnt[i] = 0;                          // reset for fill's atomic cursor
    }
    s[t] = v;
    __syncthreads();
#pragma unroll
    for (int off = 1; off < 256; off <<= 1) {
        int a = (t >= off) ? s[t - off] : 0;
        __syncthreads();
        s[t] += a;
        __syncthreads();
    }
    if (i < N_NODES) d_rowptr[i + 1] = s[t];
    if (t == 255) d_bsum[blockIdx.x] = s[255];
}

__global__ void scanB_kernel() {
    __shared__ int s[512];
    int t = threadIdx.x;
    int v = (t < NTILES) ? d_bsum[t] : 0;
    s[t] = v;
    __syncthreads();
#pragma unroll
    for (int off = 1; off < 512; off <<= 1) {
        int a = (t >= off) ? s[t - off] : 0;
        __syncthreads();
        s[t] += a;
        __syncthreads();
    }
    d_boff[t] = s[t] - v;  // exclusive
}

__global__ void scanC_kernel() {
    int i = blockIdx.x * 256 + threadIdx.x;
    if (i < N_NODES) d_rowptr[i + 1] += d_boff[blockIdx.x];
    if (i == 0) d_rowptr[0] = 0;
}

__global__ void fill_kernel() {
    int e = blockIdx.x * blockDim.x + threadIdx.x;
    if (e >= N_EDGES) return;
    int d = d_dst[e];
    int pos = d_rowptr[d] + atomicAdd(&d_cnt[d], 1);
    d_eidx[pos] = d_src[e];
}

// ---------------- tf32 tensor-core GEMM1: d_g1 = (x @ W1) * dinv ----------------
__device__ __forceinline__ unsigned f2tf32(float f) {
    unsigned u;
    asm("cvt.rna.tf32.f32 %0, %1;" : "=r"(u) : "f"(f));
    return u;
}

#define SA_STRIDE 36
#define SB_STRIDE 68

__global__ __launch_bounds__(256) void gemm1_kernel(const float* __restrict__ in,
                                                    const float* __restrict__ W) {
    float* out = d_g1;
    __shared__ unsigned sA[128 * SA_STRIDE];  // 18 KB
    __shared__ unsigned sB[32 * SB_STRIDE];   // 8.5 KB

    int tid = threadIdx.x;
    int w = tid >> 5;
    int lane = tid & 31;
    int gr = lane >> 2;   // group row 0..7
    int tg = lane & 3;    // thread-in-group 0..3
    int r0 = blockIdx.x * 128;
    int wrow = w * 16;

    float c[8][4];
#pragma unroll
    for (int j = 0; j < 8; j++)
#pragma unroll
        for (int q = 0; q < 4; q++) c[j][q] = 0.0f;

#pragma unroll
    for (int kp = 0; kp < IN_DIM / 32; kp++) {
#pragma unroll
        for (int it = 0; it < 4; it++) {
            int idx = tid + it * 256;
            int row = idx >> 3;
            int c4 = (idx & 7) * 4;
            float4 v = make_float4(0.f, 0.f, 0.f, 0.f);
            int grow = r0 + row;
            if (grow < N_NODES)
                v = *(const float4*)(in + (size_t)grow * IN_DIM + kp * 32 + c4);
            uint4 u = make_uint4(f2tf32(v.x), f2tf32(v.y), f2tf32(v.z), f2tf32(v.w));
            *(uint4*)(sA + row * SA_STRIDE + c4) = u;
        }
#pragma unroll
        for (int it = 0; it < 2; it++) {
            int idx = tid + it * 256;
            int row = idx >> 4;
            int c4 = (idx & 15) * 4;
            float4 v = *(const float4*)(W + (size_t)(kp * 32 + row) * 64 + c4);
            uint4 u = make_uint4(f2tf32(v.x), f2tf32(v.y), f2tf32(v.z), f2tf32(v.w));
            *(uint4*)(sB + row * SB_STRIDE + c4) = u;
        }
        __syncthreads();

#pragma unroll
        for (int kk = 0; kk < 32; kk += 8) {
            unsigned a0 = sA[(wrow + gr) * SA_STRIDE + kk + tg];
            unsigned a1 = sA[(wrow + gr + 8) * SA_STRIDE + kk + tg];
            unsigned a2 = sA[(wrow + gr) * SA_STRIDE + kk + tg + 4];
            unsigned a3 = sA[(wrow + gr + 8) * SA_STRIDE + kk + tg + 4];
#pragma unroll
            for (int j = 0; j < 8; j++) {
                unsigned b0 = sB[(kk + tg) * SB_STRIDE + j * 8 + gr];
                unsigned b1 = sB[(kk + tg + 4) * SB_STRIDE + j * 8 + gr];
                asm volatile(
                    "mma.sync.aligned.m16n8k8.row.col.f32.tf32.tf32.f32 "
                    "{%0,%1,%2,%3}, {%4,%5,%6,%7}, {%8,%9}, {%0,%1,%2,%3};"
                    : "+f"(c[j][0]), "+f"(c[j][1]), "+f"(c[j][2]), "+f"(c[j][3])
                    : "r"(a0), "r"(a1), "r"(a2), "r"(a3), "r"(b0), "r"(b1));
            }
        }
        __syncthreads();
    }

    int row_lo = r0 + wrow + gr;
    int row_hi = row_lo + 8;
    float dv_lo = (row_lo < N_NODES) ? d_dinv[row_lo] : 0.f;
    float dv_hi = (row_hi < N_NODES) ? d_dinv[row_hi] : 0.f;
#pragma unroll
    for (int j = 0; j < 8; j++) {
        int col = j * 8 + 2 * tg;
        if (row_lo < N_NODES) {
            float2 o = make_float2(c[j][0] * dv_lo, c[j][1] * dv_lo);
            *(float2*)(out + (size_t)row_lo * HID + col) = o;
        }
        if (row_hi < N_NODES) {
            float2 o = make_float2(c[j][2] * dv_hi, c[j][3] * dv_hi);
            *(float2*)(out + (size_t)row_hi * HID + col) = o;
        }
    }
}

// ---------------- common gather core: returns the node's aggregated float4 lane ----------------
__device__ __forceinline__ float4 gather_core(const float* __restrict__ g, int node, int lane) {
    int base = d_rowptr[node];
    int end  = d_rowptr[node + 1];

    float4 a0 = *(const float4*)(g + (size_t)node * HID + lane * 4);  // self-loop
    float4 a1 = make_float4(0.f, 0.f, 0.f, 0.f);
    float4 a2 = make_float4(0.f, 0.f, 0.f, 0.f);
    float4 a3 = make_float4(0.f, 0.f, 0.f, 0.f);

    int i = base;
    for (; i + 4 <= end; i += 4) {
        int s0 = d_eidx[i + 0];
        int s1 = d_eidx[i + 1];
        int s2 = d_eidx[i + 2];
        int s3 = d_eidx[i + 3];
        float4 v0 = *(const float4*)(g + (size_t)s0 * HID + lane * 4);
        float4 v1 = *(const float4*)(g + (size_t)s1 * HID + lane * 4);
        float4 v2 = *(const float4*)(g + (size_t)s2 * HID + lane * 4);
        float4 v3 = *(const float4*)(g + (size_t)s3 * HID + lane * 4);
        a0.x += v0.x; a0.y += v0.y; a0.z += v0.z; a0.w += v0.w;
        a1.x += v1.x; a1.y += v1.y; a1.z += v1.z; a1.w += v1.w;
        a2.x += v2.x; a2.y += v2.y; a2.z += v2.z; a2.w += v2.w;
        a3.x += v3.x; a3.y += v3.y; a3.z += v3.z; a3.w += v3.w;
    }
    for (; i < end; i++) {
        int s = d_eidx[i];
        float4 v = *(const float4*)(g + (size_t)s * HID + lane * 4);
        a0.x += v.x; a0.y += v.y; a0.z += v.z; a0.w += v.w;
    }
    return make_float4(a0.x + a1.x + a2.x + a3.x,
                       a0.y + a1.y + a2.y + a3.y,
                       a0.z + a1.z + a2.z + a3.z,
                       a0.w + a1.w + a2.w + a3.w);
}

// ---------------- gather1 + GEMM2 fused, PERSISTENT (weights loaded once/block) ----------------
// h1[n] = relu(dinv*agg(g1) + b1) (smem) → g2[n] = (h1[n] @ W2) * dinv[n]
__global__ __launch_bounds__(256) void gather_gemm2_kernel(const float* __restrict__ b1,
                                                           const float* __restrict__ W2) {
    __shared__ float sW2[HID * HID];      // 16 KB, [k][j]
    __shared__ float sH[16][HID + 4];     // h1 rows, padded

    int tid = threadIdx.x;
    for (int i = tid; i < HID * HID; i += 256) sW2[i] = W2[i];
    __syncthreads();

    int grp = tid >> 4;          // node slot 0..15
    int lane = tid & 15;
    unsigned hmask = 0xFFFFu << (threadIdx.x & 16);
    float4 bb = *(const float4*)(b1 + lane * 4);

    for (int tile = blockIdx.x; tile < N_NODE_TILES; tile += PERSIST_GRID) {
        int node = tile * 16 + grp;

        float4 sum = gather_core(d_g1, node, lane);
        float dv = d_dinv[node];
        sH[grp][lane * 4 + 0] = fmaxf(fmaf(dv, sum.x, bb.x), 0.f);
        sH[grp][lane * 4 + 1] = fmaxf(fmaf(dv, sum.y, bb.y), 0.f);
        sH[grp][lane * 4 + 2] = fmaxf(fmaf(dv, sum.z, bb.z), 0.f);
        sH[grp][lane * 4 + 3] = fmaxf(fmaf(dv, sum.w, bb.w), 0.f);
        __syncwarp(hmask);

        float c0 = 0.f, c1 = 0.f, c2 = 0.f, c3 = 0.f;
#pragma unroll 8
        for (int k = 0; k < HID; k++) {
            float hv = sH[grp][k];
            float4 w4 = *(const float4*)(sW2 + k * HID + lane * 4);
            c0 = fmaf(hv, w4.x, c0);
            c1 = fmaf(hv, w4.y, c1);
            c2 = fmaf(hv, w4.z, c2);
            c3 = fmaf(hv, w4.w, c3);
        }
        float4 o = make_float4(c0 * dv, c1 * dv, c2 * dv, c3 * dv);
        *(float4*)(d_g2 + (size_t)node * HID + lane * 4) = o;
        __syncwarp(hmask);   // protect sH before next tile overwrites it
    }
}

// ---------------- gather2 + classifier + log_softmax fused, PERSISTENT ----------------
__global__ __launch_bounds__(256) void gather_final_kernel(const float* __restrict__ b2,
                                                           const float* __restrict__ Wl,
                                                           const float* __restrict__ bl,
                                                           float* __restrict__ out) {
    __shared__ float sWl[HID * OUT_DIM];  // 10 KB, [k][j]
    __shared__ float sbl[OUT_DIM];
    __shared__ float sE[16][HID + 4];

    int tid = threadIdx.x;
    for (int i = tid; i < HID * OUT_DIM; i += 256) sWl[i] = Wl[i];
    if (tid < OUT_DIM) sbl[tid] = bl[tid];
    __syncthreads();

    int grp = tid >> 4;
    int lane = tid & 15;
    unsigned hmask = 0xFFFFu << (threadIdx.x & 16);
    float4 bb = *(const float4*)(b2 + lane * 4);
    int j0 = lane, j1 = lane + 16, j2 = lane + 32;
    float bl0 = sbl[j0];
    float bl1 = sbl[j1];
    float bl2 = (lane < 8) ? sbl[j2] : -INFINITY;

    for (int tile = blockIdx.x; tile < N_NODE_TILES; tile += PERSIST_GRID) {
        int node = tile * 16 + grp;

        float4 sum = gather_core(d_g2, node, lane);
        float dv = d_dinv[node];
        sE[grp][lane * 4 + 0] = fmaf(dv, sum.x, bb.x);
        sE[grp][lane * 4 + 1] = fmaf(dv, sum.y, bb.y);
        sE[grp][lane * 4 + 2] = fmaf(dv, sum.z, bb.z);
        sE[grp][lane * 4 + 3] = fmaf(dv, sum.w, bb.w);
        __syncwarp(hmask);

        float l0 = bl0, l1 = bl1, l2 = bl2;
#pragma unroll 8
        for (int k = 0; k < HID; k++) {
            float ev = sE[grp][k];
            l0 = fmaf(ev, sWl[k * OUT_DIM + j0], l0);
            l1 = fmaf(ev, sWl[k * OUT_DIM + j1], l1);
            if (lane < 8) l2 = fmaf(ev, sWl[k * OUT_DIM + j2], l2);
        }
        float m = fmaxf(l0, fmaxf(l1, l2));
#pragma unroll
        for (int o = 8; o; o >>= 1) m = fmaxf(m, __shfl_xor_sync(hmask, m, o));
        float s = expf(l0 - m) + expf(l1 - m) + ((lane < 8) ? expf(l2 - m) : 0.0f);
#pragma unroll
        for (int o = 8; o; o >>= 1) s += __shfl_xor_sync(hmask, s, o);
        float lse = m + logf(s);

        float* orow = out + (size_t)node * OUT_DIM;
        orow[j0] = l0 - lse;
        orow[j1] = l1 - lse;
        if (lane < 8) orow[j2] = l2 - lse;
        __syncwarp(hmask);   // protect sE before next tile overwrites it
    }
}

extern "C" void kernel_launch(void* const* d_in, const int* in_sizes, int n_in,
                              void* d_out, int out_size) {
    const float* x = (const float*)d_in[0];
    const int* ei32 = (const int*)d_in[1];   // int32 OR int64 — detected on device
    const float* W1 = (const float*)d_in[2];
    const float* b1 = (const float*)d_in[3];
    const float* W2 = (const float*)d_in[4];
    const float* b2 = (const float*)d_in[5];
    const float* Wl = (const float*)d_in[6];
    const float* bl = (const float*)d_in[7];
    float* out = (float*)d_out;

    // canonicalize + CSR build + norms
    detect_zero_kernel<<<NTILES, 256>>>(ei32);
    convert_hist_kernel<<<(N_EDGES + 255) / 256, 256>>>(ei32);
    scanA_kernel<<<NTILES, 256>>>();
    scanB_kernel<<<1, 512>>>();
    scanC_kernel<<<NTILES, 256>>>();
    fill_kernel<<<(N_EDGES + 255) / 256, 256>>>();

    // layer 1 projection (tensor cores)
    gemm1_kernel<<<(N_NODES + 127) / 128, 256>>>(x, W1);
    // layer-1 aggregate + layer-2 projection (fused, persistent)
    gather_gemm2_kernel<<<PERSIST_GRID, 256>>>(b1, W2);
    // layer-2 aggregate + classifier + log_softmax (fused, persistent)
    gather_final_kernel<<<PERSIST_GRID, 256>>>(b2, Wl, bl, out);
}

// round 16
// speedup vs baseline: 1.0953x; 1.0953x over previous
#include <cuda_runtime.h>
#include <cuda_fp16.h>
#include <math.h>

#define N_NODES 100000
#define N_EDGES 1600000
#define IN_DIM 128
#define HID 64
#define OUT_DIM 40
#define NTILES ((N_NODES + 255) / 256)   // 391

// ---------------- scratch (__device__ globals; referenced from DEVICE code only) ----------------
__device__ int d_is64;                         // 1 if edge_index delivered as int64
__device__ int d_gctr;                         // global cursor for tile-base assignment
__device__ __align__(16) int d_src[N_EDGES];   // canonical int32 src
__device__ __align__(16) int d_dst[N_EDGES];   // canonical int32 dst
__device__ __align__(16) int d_cnt[N_NODES];
__device__ __align__(16) int d_rowstart[N_NODES];
__device__ __align__(16) int d_deg[N_NODES];
__device__ __align__(16) int d_eidx[N_EDGES];
__device__ __align__(16) float d_dinv[N_NODES];
__device__ __align__(16) __half d_g1h[(size_t)N_NODES * HID];  // (x@W1)*dinv, fp16
__device__ __align__(16) __half d_g2h[(size_t)N_NODES * HID];  // (h1@W2)*dinv, fp16
__device__ __align__(16) float d_h1[(size_t)N_NODES * HID];    // relu(dinv*agg + b1)
__device__ __align__(16) float d_emb[(size_t)N_NODES * HID];   // dinv*agg + b2

// ---------------- detect dtype + zero d_cnt + zero cursor (fused) ----------------
__global__ void detect_zero_kernel(const int* __restrict__ ei32) {
    int i = blockIdx.x * blockDim.x + threadIdx.x;
    if (i < N_NODES) d_cnt[i] = 0;
    if (i == 0) d_gctr = 0;
    if (blockIdx.x == 0) {
        __shared__ int any_nonzero;
        if (threadIdx.x == 0) any_nonzero = 0;
        __syncthreads();
        int local = 0;
        for (int k = threadIdx.x; k < 2048; k += blockDim.x)
            local |= ei32[2 * k + 1];
        if (local) atomicOr(&any_nonzero, 1);
        __syncthreads();
        if (threadIdx.x == 0) d_is64 = (any_nonzero == 0) ? 1 : 0;
    }
}

// convert to canonical int32 + in-degree histogram, one pass
__global__ void convert_hist_kernel(const int* __restrict__ ei32) {
    int e = blockIdx.x * blockDim.x + threadIdx.x;
    if (e >= N_EDGES) return;
    int s, d;
    if (d_is64) {   // coalesced 8B loads; low word holds the value (LE)
        const long long* e64 = (const long long*)ei32;
        s = (int)e64[e];
        d = (int)e64[N_EDGES + e];
    } else {
        s = ei32[e];
        d = ei32[N_EDGES + e];
    }
    s = min(max(s, 0), N_NODES - 1);   // clamp: no wild addresses downstream
    d = min(max(d, 0), N_NODES - 1);
    d_src[e] = s;
    d_dst[e] = d;
    atomicAdd(&d_cnt[d], 1);
}

// ONE-launch scan: per-tile local scan + atomic tile-base claim.
// CSR bucket ordering across nodes is irrelevant for a sum, so tile bases may be
// claimed in any order. Also emits dinv, deg, and re-zeroes d_cnt.
__global__ void scan_fused_kernel() {
    __shared__ int s[256];
    __shared__ int sbase;
    int t = threadIdx.x;
    int i = blockIdx.x * 256 + t;
    int v = (i < N_NODES) ? d_cnt[i] : 0;
    if (i < N_NODES) {
        d_dinv[i] = rsqrtf((float)v + 1.0f);  // +1 self-loop
        d_deg[i] = v;
        d_cnt[i] = 0;                          // reset for fill's atomic cursor
    }
    s[t] = v;
    __syncthreads();
#pragma unroll
    for (int off = 1; off < 256; off <<= 1) {
        int a = (t >= off) ? s[t - off] : 0;
        __syncthreads();
        s[t] += a;
        __syncthreads();
    }
    if (t == 255) sbase = atomicAdd(&d_gctr, s[255]);
    __syncthreads();
    if (i < N_NODES) d_rowstart[i] = sbase + s[t] - v;  // exclusive scan + base
}

__global__ void fill_kernel() {
    int e = blockIdx.x * blockDim.x + threadIdx.x;
    if (e >= N_EDGES) return;
    int d = d_dst[e];
    int pos = d_rowstart[d] + atomicAdd(&d_cnt[d], 1);
    d_eidx[pos] = d_src[e];
}

// ---------------- tf32 tensor-core GEMM: out_fp16 = (in @ W) * dinv ----------------
__device__ __forceinline__ unsigned f2tf32(float f) {
    unsigned u;
    asm("cvt.rna.tf32.f32 %0, %1;" : "=r"(u) : "f"(f));
    return u;
}

#define SA_STRIDE 36
#define SB_STRIDE 68

// LAYER 0: in = xin (param), out = d_g1h.  LAYER 1: in = d_h1, out = d_g2h.
template <int KDIM, int LAYER>
__global__ __launch_bounds__(256) void gemm_kernel(const float* __restrict__ xin,
                                                   const float* __restrict__ W) {
    const float* in = (LAYER == 0) ? xin : d_h1;
    __half* out = (LAYER == 0) ? d_g1h : d_g2h;

    __shared__ unsigned sA[128 * SA_STRIDE];  // 18 KB
    __shared__ unsigned sB[32 * SB_STRIDE];   // 8.5 KB

    int tid = threadIdx.x;
    int w = tid >> 5;
    int lane = tid & 31;
    int gr = lane >> 2;   // group row 0..7
    int tg = lane & 3;    // thread-in-group 0..3
    int r0 = blockIdx.x * 128;
    int wrow = w * 16;

    float c[8][4];
#pragma unroll
    for (int j = 0; j < 8; j++)
#pragma unroll
        for (int q = 0; q < 4; q++) c[j][q] = 0.0f;

#pragma unroll
    for (int kp = 0; kp < KDIM / 32; kp++) {
#pragma unroll
        for (int it = 0; it < 4; it++) {
            int idx = tid + it * 256;
            int row = idx >> 3;
            int c4 = (idx & 7) * 4;
            float4 v = make_float4(0.f, 0.f, 0.f, 0.f);
            int grow = r0 + row;
            if (grow < N_NODES)
                v = *(const float4*)(in + (size_t)grow * KDIM + kp * 32 + c4);
            uint4 u = make_uint4(f2tf32(v.x), f2tf32(v.y), f2tf32(v.z), f2tf32(v.w));
            *(uint4*)(sA + row * SA_STRIDE + c4) = u;
        }
#pragma unroll
        for (int it = 0; it < 2; it++) {
            int idx = tid + it * 256;
            int row = idx >> 4;
            int c4 = (idx & 15) * 4;
            float4 v = *(const float4*)(W + (size_t)(kp * 32 + row) * 64 + c4);
            uint4 u = make_uint4(f2tf32(v.x), f2tf32(v.y), f2tf32(v.z), f2tf32(v.w));
            *(uint4*)(sB + row * SB_STRIDE + c4) = u;
        }
        __syncthreads();

#pragma unroll
        for (int kk = 0; kk < 32; kk += 8) {
            unsigned a0 = sA[(wrow + gr) * SA_STRIDE + kk + tg];
            unsigned a1 = sA[(wrow + gr + 8) * SA_STRIDE + kk + tg];
            unsigned a2 = sA[(wrow + gr) * SA_STRIDE + kk + tg + 4];
            unsigned a3 = sA[(wrow + gr + 8) * SA_STRIDE + kk + tg + 4];
#pragma unroll
            for (int j = 0; j < 8; j++) {
                unsigned b0 = sB[(kk + tg) * SB_STRIDE + j * 8 + gr];
                unsigned b1 = sB[(kk + tg + 4) * SB_STRIDE + j * 8 + gr];
                asm volatile(
                    "mma.sync.aligned.m16n8k8.row.col.f32.tf32.tf32.f32 "
                    "{%0,%1,%2,%3}, {%4,%5,%6,%7}, {%8,%9}, {%0,%1,%2,%3};"
                    : "+f"(c[j][0]), "+f"(c[j][1]), "+f"(c[j][2]), "+f"(c[j][3])
                    : "r"(a0), "r"(a1), "r"(a2), "r"(a3), "r"(b0), "r"(b1));
            }
        }
        __syncthreads();
    }

    int row_lo = r0 + wrow + gr;
    int row_hi = row_lo + 8;
    float dv_lo = (row_lo < N_NODES) ? d_dinv[row_lo] : 0.f;
    float dv_hi = (row_hi < N_NODES) ? d_dinv[row_hi] : 0.f;
#pragma unroll
    for (int j = 0; j < 8; j++) {
        int col = j * 8 + 2 * tg;
        if (row_lo < N_NODES) {
            __half2 h = __floats2half2_rn(c[j][0] * dv_lo, c[j][1] * dv_lo);
            *(__half2*)(out + (size_t)row_lo * HID + col) = h;
        }
        if (row_hi < N_NODES) {
            __half2 h = __floats2half2_rn(c[j][2] * dv_hi, c[j][3] * dv_hi);
            *(__half2*)(out + (size_t)row_hi * HID + col) = h;
        }
    }
}

// ---------------- fp16 row-lane load: 4 halves (8B) -> float4 ----------------
__device__ __forceinline__ float4 h4load(const __half* __restrict__ g, int row, int lane) {
    uint2 u = *(const uint2*)(g + (size_t)row * HID + lane * 4);
    float2 f0 = __half22float2(*(__half2*)&u.x);
    float2 f1 = __half22float2(*(__half2*)&u.y);
    return make_float4(f0.x, f0.y, f1.x, f1.y);
}

// ---------------- gather core (fp16 features, fp32 accumulate) ----------------
__device__ __forceinline__ float4 gather_core(const __half* __restrict__ g, int node, int lane) {
    int base = d_rowstart[node];
    int end  = base + d_deg[node];

    float4 a0 = h4load(g, node, lane);  // self-loop
    float4 a1 = make_float4(0.f, 0.f, 0.f, 0.f);
    float4 a2 = make_float4(0.f, 0.f, 0.f, 0.f);
    float4 a3 = make_float4(0.f, 0.f, 0.f, 0.f);

    int i = base;
    for (; i + 4 <= end; i += 4) {
        int s0 = d_eidx[i + 0];
        int s1 = d_eidx[i + 1];
        int s2 = d_eidx[i + 2];
        int s3 = d_eidx[i + 3];
        float4 v0 = h4load(g, s0, lane);
        float4 v1 = h4load(g, s1, lane);
        float4 v2 = h4load(g, s2, lane);
        float4 v3 = h4load(g, s3, lane);
        a0.x += v0.x; a0.y += v0.y; a0.z += v0.z; a0.w += v0.w;
        a1.x += v1.x; a1.y += v1.y; a1.z += v1.z; a1.w += v1.w;
        a2.x += v2.x; a2.y += v2.y; a2.z += v2.z; a2.w += v2.w;
        a3.x += v3.x; a3.y += v3.y; a3.z += v3.z; a3.w += v3.w;
    }
    for (; i < end; i++) {
        int s = d_eidx[i];
        float4 v = h4load(g, s, lane);
        a0.x += v.x; a0.y += v.y; a0.z += v.z; a0.w += v.w;
    }
    return make_float4(a0.x + a1.x + a2.x + a3.x,
                       a0.y + a1.y + a2.y + a3.y,
                       a0.z + a1.z + a2.z + a3.z,
                       a0.w + a1.w + a2.w + a3.w);
}

// ---------------- gather: out[n] = post(dinv[n]*agg + bias) ----------------
// LAYER 0: g=d_g1h, out=d_h1 (relu).  LAYER 1: g=d_g2h, out=d_emb.
// 16 nodes/block, 16 threads/node; N_NODES = 16*6250 exactly.
template <int LAYER>
__global__ __launch_bounds__(256) void gather_kernel(const float* __restrict__ bias) {
    const __half* g = (LAYER == 0) ? d_g1h : d_g2h;
    float* out = (LAYER == 0) ? d_h1 : d_emb;

    int t = threadIdx.x;
    int node = blockIdx.x * 16 + (t >> 4);
    int lane = t & 15;

    float4 sum = gather_core(g, node, lane);
    float dv = d_dinv[node];
    float4 bb = *(const float4*)(bias + lane * 4);
    float4 o;
    o.x = fmaf(dv, sum.x, bb.x);
    o.y = fmaf(dv, sum.y, bb.y);
    o.z = fmaf(dv, sum.z, bb.z);
    o.w = fmaf(dv, sum.w, bb.w);
    if (LAYER == 0) {
        o.x = fmaxf(o.x, 0.f); o.y = fmaxf(o.y, 0.f);
        o.z = fmaxf(o.z, 0.f); o.w = fmaxf(o.w, 0.f);
    }
    *(float4*)(out + (size_t)node * HID + lane * 4) = o;
}

// ---------------- final: logits = emb@Wl + bl; log_softmax. one warp/node ----------------
__global__ __launch_bounds__(256) void final_kernel(const float* __restrict__ Wl,
                                                    const float* __restrict__ bl,
                                                    float* __restrict__ out) {
    __shared__ float sWl[HID * OUT_DIM];
    __shared__ float sbl[OUT_DIM];
    __shared__ float semb[8][HID];
    int tid = threadIdx.x;
    for (int i = tid; i < HID * OUT_DIM; i += 256) sWl[i] = Wl[i];
    if (tid < OUT_DIM) sbl[tid] = bl[tid];
    __syncthreads();

    int w = tid >> 5, lane = tid & 31;
    int n = blockIdx.x * 8 + w;
    if (n >= N_NODES) return;

    float e0 = d_emb[(size_t)n * HID + lane];
    float e1 = d_emb[(size_t)n * HID + 32 + lane];
    semb[w][lane] = e0;
    semb[w][32 + lane] = e1;
    __syncwarp();

    float v0 = sbl[lane];
    float v1 = (lane < 8) ? sbl[32 + lane] : -INFINITY;
#pragma unroll 8
    for (int k = 0; k < HID; k++) {
        float ev = semb[w][k];
        v0 = fmaf(ev, sWl[k * OUT_DIM + lane], v0);
        if (lane < 8) v1 = fmaf(ev, sWl[k * OUT_DIM + 32 + lane], v1);
    }
    float m = fmaxf(v0, v1);
#pragma unroll
    for (int o = 16; o; o >>= 1) m = fmaxf(m, __shfl_xor_sync(0xffffffffu, m, o));
    float s = expf(v0 - m) + ((lane < 8) ? expf(v1 - m) : 0.0f);
#pragma unroll
    for (int o = 16; o; o >>= 1) s += __shfl_xor_sync(0xffffffffu, s, o);
    float lse = m + logf(s);

    out[(size_t)n * OUT_DIM + lane] = v0 - lse;
    if (lane < 8) out[(size_t)n * OUT_DIM + 32 + lane] = v1 - lse;
}

extern "C" void kernel_launch(void* const* d_in, const int* in_sizes, int n_in,
                              void* d_out, int out_size) {
    const float* x = (const float*)d_in[0];
    const int* ei32 = (const int*)d_in[1];   // int32 OR int64 — detected on device
    const float* W1 = (const float*)d_in[2];
    const float* b1 = (const float*)d_in[3];
    const float* W2 = (const float*)d_in[4];
    const float* b2 = (const float*)d_in[5];
    const float* Wl = (const float*)d_in[6];
    const float* bl = (const float*)d_in[7];
    float* out = (float*)d_out;

    // canonicalize + CSR build + norms (4 launches)
    detect_zero_kernel<<<NTILES, 256>>>(ei32);
    convert_hist_kernel<<<(N_EDGES + 255) / 256, 256>>>(ei32);
    scan_fused_kernel<<<NTILES, 256>>>();
    fill_kernel<<<(N_EDGES + 255) / 256, 256>>>();

    // layer 1
    gemm_kernel<IN_DIM, 0><<<(N_NODES + 127) / 128, 256>>>(x, W1);
    gather_kernel<0><<<N_NODES / 16, 256>>>(b1);

    // layer 2
    gemm_kernel<HID, 1><<<(N_NODES + 127) / 128, 256>>>(nullptr, W2);
    gather_kernel<1><<<N_NODES / 16, 256>>>(b2);

    // classifier + log_softmax
    final_kernel<<<(N_NODES + 7) / 8, 256>>>(Wl, bl, out);
}